// round 3
// baseline (speedup 1.0000x reference)
#include <cuda_runtime.h>
#include <cuda_fp16.h>

#define NROWS 100000
#define D     128
#define PP    8192
#define NEG   256
#define TEMPF 0.07f

// Scratch (device globals: allocation-free per harness rules)
__device__ __align__(16) float  g_emb [ (size_t)NROWS * D ];   // fp32 projected embeddings (51.2 MB)
__device__ __align__(16) __half g_embh[ (size_t)NROWS * D ];   // fp16 copy for negative gathers (25.6 MB)
__device__ float g_losses[2 * PP];

union U64 { unsigned long long u; float2 f; };

__device__ __forceinline__ unsigned long long fma2(unsigned long long a,
                                                   unsigned long long b,
                                                   unsigned long long c) {
    unsigned long long d;
    asm("fma.rn.f32x2 %0, %1, %2, %3;" : "=l"(d) : "l"(a), "l"(b), "l"(c));
    return d;
}

// ---------------------------------------------------------------------------
// Kernel 1: emb = X @ W^T + b   (fp32, f32x2 packed FMA)
// Block: 256 threads, 32 rows per block. Warp w owns rows w*4..w*4+3,
// lane owns dims lane*4..lane*4+3. W transposed+padded in shared.
// ---------------------------------------------------------------------------
__global__ void gemm_kernel(const float* __restrict__ X,
                            const float* __restrict__ W,
                            const float* __restrict__ b) {
    extern __shared__ float sh[];
    float* Wt = sh;               // [128][132] transposed, padded
    float* Xs = sh + 128 * 132;   // [32][128]
    __shared__ float bs[D];

    int tid  = threadIdx.x;
    int lane = tid & 31;
    int warp = tid >> 5;

    // load W transposed: Wt[k*132 + d] = W[d*128 + k]
    for (int i = tid; i < D * D; i += 256) {
        int d = i >> 7, k = i & 127;
        Wt[k * 132 + d] = W[i];
    }
    if (tid < D) bs[tid] = b[tid];

    int row0 = blockIdx.x * 32;
    {
        const float4* Xg  = (const float4*)(X + (size_t)row0 * D);
        float4*       Xs4 = (float4*)Xs;
        for (int i = tid; i < 32 * D / 4; i += 256) Xs4[i] = Xg[i];
    }
    __syncthreads();

    int d0 = lane * 4;
    U64 acc[4][2];
    {
        U64 b01, b23;
        b01.f = make_float2(bs[d0],     bs[d0 + 1]);
        b23.f = make_float2(bs[d0 + 2], bs[d0 + 3]);
#pragma unroll
        for (int r = 0; r < 4; r++) { acc[r][0] = b01; acc[r][1] = b23; }
    }
    int rbase = warp * 4;

#pragma unroll 8
    for (int k = 0; k < D; k++) {
        float4 wv = *(const float4*)(Wt + k * 132 + d0);
        U64 w01, w23;
        w01.f = make_float2(wv.x, wv.y);
        w23.f = make_float2(wv.z, wv.w);
#pragma unroll
        for (int r = 0; r < 4; r++) {
            float xv = Xs[(rbase + r) * D + k];
            U64 xx; xx.f = make_float2(xv, xv);
            acc[r][0].u = fma2(xx.u, w01.u, acc[r][0].u);
            acc[r][1].u = fma2(xx.u, w23.u, acc[r][1].u);
        }
    }

#pragma unroll
    for (int r = 0; r < 4; r++) {
        size_t off = (size_t)(row0 + rbase + r) * D + d0;
        float4 o;
        o.x = acc[r][0].f.x; o.y = acc[r][0].f.y;
        o.z = acc[r][1].f.x; o.w = acc[r][1].f.y;
        *(float4*)(g_emb + off) = o;
        __half2 h01 = __floats2half2_rn(o.x, o.y);
        __half2 h23 = __floats2half2_rn(o.z, o.w);
        uint2 hv;
        hv.x = *(unsigned int*)&h01;
        hv.y = *(unsigned int*)&h23;
        *(uint2*)(g_embh + off) = hv;
    }
}

// ---------------------------------------------------------------------------
// Kernel 2: per (p, branch): logits, logsumexp, per-pair loss.
// Block = 256 threads. Each warp handles 2 negatives per iteration
// (16 lanes per negative: uint4 = 8 halves each, xor-reduce over 16 lanes).
// ---------------------------------------------------------------------------
__global__ void branch_kernel(const int* __restrict__ pos_anchor,
                              const int* __restrict__ pos_partner,
                              const int* __restrict__ neg_idx,
                              const int* __restrict__ weak_anchor,
                              const int* __restrict__ weak_partner,
                              const int* __restrict__ weak_neg_idx) {
    __shared__ float qsh[D], ksh[D];
    __shared__ int   sidx[NEG];
    __shared__ float sdots[NEG + 1];
    __shared__ float sred[9];

    int p  = blockIdx.x;
    int br = blockIdx.y;
    const int* anc = br ? weak_anchor  : pos_anchor;
    const int* par = br ? weak_partner : pos_partner;
    const int* nix = br ? weak_neg_idx : neg_idx;

    int tid  = threadIdx.x;
    int lane = tid & 31;
    int warp = tid >> 5;

    int a  = anc[p];
    int pr = par[p];
    if (tid < D) qsh[tid]     = g_emb[(size_t)a  * D + tid];
    else         ksh[tid - D] = g_emb[(size_t)pr * D + (tid - D)];
    sidx[tid] = nix[(size_t)p * NEG + tid];
    __syncthreads();

    int hl   = lane & 15;
    int half = lane >> 4;

    float qr[8];
#pragma unroll
    for (int j = 0; j < 8; j++) qr[j] = qsh[hl * 8 + j];

    // positive dot in fp32 (warp 0)
    if (warp == 0) {
        float s = 0.f;
#pragma unroll
        for (int j = 0; j < 4; j++) s += qsh[lane * 4 + j] * ksh[lane * 4 + j];
#pragma unroll
        for (int m = 16; m >= 1; m >>= 1) s += __shfl_xor_sync(0xffffffffu, s, m);
        if (lane == 0) sdots[NEG] = s;
    }

    // negatives: fp16 rows, fp32 q and fp32 accumulation
#pragma unroll 4
    for (int it = 0; it < 16; it++) {
        int n   = warp * 32 + it * 2 + half;
        int row = sidx[n];
        uint4 v = *(const uint4*)(g_embh + (size_t)row * D + hl * 8);
        __half2* h2 = (__half2*)&v;
        float s = 0.f;
#pragma unroll
        for (int j = 0; j < 4; j++) {
            float2 f = __half22float2(h2[j]);
            s = fmaf(qr[2 * j],     f.x, s);
            s = fmaf(qr[2 * j + 1], f.y, s);
        }
        s += __shfl_xor_sync(0xffffffffu, s, 8);
        s += __shfl_xor_sync(0xffffffffu, s, 4);
        s += __shfl_xor_sync(0xffffffffu, s, 2);
        s += __shfl_xor_sync(0xffffffffu, s, 1);
        if (hl == 0) sdots[n] = s;
    }
    __syncthreads();

    const float invT = 1.0f / TEMPF;

    // max over all 257 dots
    float v = sdots[tid];
    float mv = (tid == 0) ? fmaxf(v, sdots[NEG]) : v;
#pragma unroll
    for (int m = 16; m >= 1; m >>= 1) mv = fmaxf(mv, __shfl_xor_sync(0xffffffffu, mv, m));
    if (lane == 0) sred[warp] = mv;
    __syncthreads();
    if (tid == 0) {
        float m2 = sred[0];
#pragma unroll
        for (int i = 1; i < 8; i++) m2 = fmaxf(m2, sred[i]);
        sred[8] = m2;
    }
    __syncthreads();
    float ml = sred[8] * invT;   // max logit

    // sum of exp(logit - ml)
    float e = expf(v * invT - ml);
    if (tid == 0) e += expf(sdots[NEG] * invT - ml);
#pragma unroll
    for (int m = 16; m >= 1; m >>= 1) e += __shfl_xor_sync(0xffffffffu, e, m);
    if (lane == 0) sred[warp] = e;
    __syncthreads();
    if (tid == 0) {
        float s = 0.f;
#pragma unroll
        for (int i = 0; i < 8; i++) s += sred[i];
        g_losses[br * PP + p] = ml + logf(s) - sdots[NEG] * invT;
    }
}

// ---------------------------------------------------------------------------
// Kernel 3: deterministic mean reduction, out = mean0 + 0.1 * mean1
// ---------------------------------------------------------------------------
__global__ void finalize_kernel(float* __restrict__ out) {
    __shared__ double s0sh[256], s1sh[256];
    int tid = threadIdx.x;
    double s0 = 0.0, s1 = 0.0;
    for (int i = tid; i < PP; i += 256) {
        s0 += (double)g_losses[i];
        s1 += (double)g_losses[PP + i];
    }
    s0sh[tid] = s0; s1sh[tid] = s1;
    __syncthreads();
    for (int st = 128; st > 0; st >>= 1) {
        if (tid < st) { s0sh[tid] += s0sh[tid + st]; s1sh[tid] += s1sh[tid + st]; }
        __syncthreads();
    }
    if (tid == 0)
        out[0] = (float)(s0sh[0] / (double)PP + 0.1 * (s1sh[0] / (double)PP));
}

extern "C" void kernel_launch(void* const* d_in, const int* in_sizes, int n_in,
                              void* d_out, int out_size) {
    const float* X  = (const float*)d_in[0];
    const float* W  = (const float*)d_in[1];
    const float* b  = (const float*)d_in[2];
    const int*   pa = (const int*)d_in[3];
    const int*   pp = (const int*)d_in[4];
    const int*   ni = (const int*)d_in[5];
    const int*   wa = (const int*)d_in[6];
    const int*   wp = (const int*)d_in[7];
    const int*   wn = (const int*)d_in[8];
    float* out = (float*)d_out;

    size_t smem = (size_t)(128 * 132 + 32 * 128) * sizeof(float);  // 83968 B
    cudaFuncSetAttribute(gemm_kernel, cudaFuncAttributeMaxDynamicSharedMemorySize, (int)smem);

    gemm_kernel<<<NROWS / 32, 256, smem>>>(X, W, b);
    branch_kernel<<<dim3(PP, 2), 256>>>(pa, pp, ni, wa, wp, wn);
    finalize_kernel<<<1, 256>>>(out);
}